// round 13
// baseline (speedup 1.0000x reference)
#include <cuda_runtime.h>
#include <cuda_bf16.h>
#include <math.h>

#define Tn 128
#define Bn 2048
#define Hn 256
#define In0 18
#define G3H 768
#define XP 32          // x K padded to 32 (one half-chunk)
#define NT 512

typedef unsigned int u32;

// ---------------- device global scratch ----------------
__device__ float          g_h1f[2][Bn * Hn], g_h2f[2][Bn * Hn];
__device__ __nv_bfloat16  g_h1h[2][Bn * Hn], g_h1l[2][Bn * Hn];
__device__ __nv_bfloat16  g_h2h[2][Bn * Hn], g_h2l[2][Bn * Hn];
__device__ __nv_bfloat16  g_whh0h[G3H * Hn], g_whh0l[G3H * Hn];
__device__ __nv_bfloat16  g_wih1h[G3H * Hn], g_wih1l[G3H * Hn];
__device__ __nv_bfloat16  g_whh1h[G3H * Hn], g_whh1l[G3H * Hn];
__device__ __nv_bfloat16  g_wi0h[G3H * XP],  g_wi0l[G3H * XP];
__device__ __nv_bfloat16  g_xsh[(size_t)Tn * Bn * XP], g_xsl[(size_t)Tn * Bn * XP];
__device__ unsigned       g_bar[32];

__device__ __forceinline__ float sigf(float x) { return 1.f / (1.f + expf(-x)); }
__device__ __forceinline__ float tanha(float x) {
    float y; asm("tanh.approx.f32 %0, %1;" : "=f"(y) : "f"(x)); return y;
}
__device__ __forceinline__ float siga(float x) { return fmaf(tanha(0.5f * x), 0.5f, 0.5f); }

// ---------------- PTX helpers ----------------
__device__ __forceinline__ u32 s2u(const void* p) { return (u32)__cvta_generic_to_shared(p); }
__device__ __forceinline__ void ldsm4(u32 (&d)[4], u32 addr) {
    asm volatile("ldmatrix.sync.aligned.m8n8.x4.shared.b16 {%0,%1,%2,%3}, [%4];"
                 : "=r"(d[0]), "=r"(d[1]), "=r"(d[2]), "=r"(d[3]) : "r"(addr));
}
__device__ __forceinline__ void cpa(u32 dst, const void* src) {
    asm volatile("cp.async.cg.shared.global [%0], [%1], 16;" :: "r"(dst), "l"(src));
}
__device__ __forceinline__ void mma(float (&d)[4], const u32 (&a)[4], u32 b0, u32 b1) {
    asm("mma.sync.aligned.m16n8k16.row.col.f32.bf16.bf16.f32 "
        "{%0,%1,%2,%3},{%4,%5,%6,%7},{%8,%9},{%0,%1,%2,%3};"
        : "+f"(d[0]), "+f"(d[1]), "+f"(d[2]), "+f"(d[3])
        : "r"(a[0]), "r"(a[1]), "r"(a[2]), "r"(a[3]), "r"(b0), "r"(b1));
}

// smem: 2 buffers x 64KB. Buffer: A hi | A lo | W hi | W lo.
#define BUFB 65536
#define SMEM_DYN (2 * BUFB)

// ---------------- staging (QW quads per row: 8 => K64, 4 => K32) ----------------
template<int QW>
__device__ __forceinline__ void stage_chunk(
    u32 base, int tid, int j0,
    const __nv_bfloat16* __restrict__ Ah, const __nv_bfloat16* __restrict__ Al, int lda,
    const __nv_bfloat16* __restrict__ Wh, const __nv_bfloat16* __restrict__ Wl, int ldw)
{
    const u32 aH = base, aL = base + QW * 1024;
    const u32 wH = base + 16384, wL = wH + QW * 192 * 16;
    // A: 64*QW slots
    if (QW == 8 || tid < 64 * QW) {
        const int r = tid / QW, q = tid % QW;
        const u32 off = (u32)((r * QW + (q ^ (r & (QW - 1)))) * 16);
        cpa(aH + off, Ah + (size_t)r * lda + q * 8);
        cpa(aL + off, Al + (size_t)r * lda + q * 8);
    }
    // W: 192*QW slots
    #pragma unroll
    for (int i = 0; i < (192 * QW + NT - 1) / NT; ++i) {
        const int idx = tid + i * NT;
        if (idx < 192 * QW) {
            const int cl = idx / QW, q = idx % QW;
            const int grow = (cl >> 6) * Hn + j0 + (cl & 63);
            const u32 off = (u32)((cl * QW + (q ^ (cl & (QW - 1)))) * 16);
            cpa(wH + off, Wh + (size_t)grow * ldw + q * 8);
            cpa(wL + off, Wl + (size_t)grow * ldw + q * 8);
        }
    }
    asm volatile("cp.async.commit_group;");
}

// resolve chunk source & stage. k: 0=x-chunk(QW4), 1..4 whh0, 5..8 wih1, 9..12 whh1.
__device__ __forceinline__ void stage_any(int k, int l, u32 base, int tid, int b0, int j0)
{
    const int pv = (l + 1) & 1, cu = l & 1;
    if (k == 0) {
        stage_chunk<4>(base, tid, j0,
                       g_xsh + ((size_t)l * Bn + b0) * XP, g_xsl + ((size_t)l * Bn + b0) * XP, XP,
                       g_wi0h, g_wi0l, XP);
    } else if (k <= 4) {
        const int c = k - 1;
        stage_chunk<8>(base, tid, j0,
                       g_h1h[pv] + (size_t)b0 * Hn + c * 64, g_h1l[pv] + (size_t)b0 * Hn + c * 64, Hn,
                       g_whh0h + c * 64, g_whh0l + c * 64, Hn);
    } else if (k <= 8) {
        const int c = k - 5;
        stage_chunk<8>(base, tid, j0,
                       g_h1h[pv] + (size_t)b0 * Hn + c * 64, g_h1l[pv] + (size_t)b0 * Hn + c * 64, Hn,
                       g_wih1h + c * 64, g_wih1l + c * 64, Hn);
    } else {
        const int c = k - 9;
        stage_chunk<8>(base, tid, j0,
                       g_h2h[cu] + (size_t)b0 * Hn + c * 64, g_h2l[cu] + (size_t)b0 * Hn + c * 64, Hn,
                       g_whh1h + c * 64, g_whh1l + c * 64, Hn);
    }
}

// ---------------- compute (acc sets: 0=R 1=Z 2=XN 3=HN; NSEL = dest for gate n) ----------------
// warp tile: m16 (rows wm*16) x n16 per gate (cols wn*16).
template<int QW, int NSEL>
__device__ __forceinline__ void compute_chunk(
    u32 base, int lane, int wm, int wn, float (&acc)[4][2][4])
{
    const u32 aH = base, aL = base + QW * 1024;
    const u32 wH = base + 16384, wL = wH + QW * 192 * 16;
    const int arow_f = (lane & 7) + ((lane >> 3) & 1) * 8;
    const int akg    = (lane >> 4) & 1;
    const int brow_f = (lane & 7) + ((lane >> 4) & 1) * 8;
    const int bkg    = (lane >> 3) & 1;
    #pragma unroll
    for (int s = 0; s < QW / 2; ++s) {
        u32 ah[4], al[4];
        {
            const int r = wm * 16 + arow_f;
            const int g = s * 2 + akg;
            const u32 off = (u32)((r * QW + (g ^ (r & (QW - 1)))) * 16);
            ldsm4(ah, aH + off);
            ldsm4(al, aL + off);
        }
        #pragma unroll
        for (int g3 = 0; g3 < 3; ++g3) {
            const int set = (g3 == 2) ? NSEL : g3;
            const int cl = g3 * 64 + wn * 16 + brow_f;
            const int g = s * 2 + bkg;
            const u32 off = (u32)((cl * QW + (g ^ (cl & (QW - 1)))) * 16);
            u32 bh[4], bl[4];
            ldsm4(bh, wH + off);
            ldsm4(bl, wL + off);
            // 3 passes: hi*hi, lo*hi, hi*lo — 2 independent accs between same-acc reuse
            #pragma unroll
            for (int p = 0; p < 3; ++p) {
                const u32 (&aa)[4] = (p == 1) ? al : ah;
                const u32 (&bb)[4] = (p == 2) ? bl : bh;
                mma(acc[set][0], aa, bb[0], bb[1]);
                mma(acc[set][1], aa, bb[2], bb[3]);
            }
        }
    }
}

// ---------------- GRU gate epilogue ----------------
__device__ __forceinline__ void epilogue(
    const float* __restrict__ bih, const float* __restrict__ bhh,
    const float* __restrict__ hpf, float* __restrict__ hof,
    __nv_bfloat16* __restrict__ hoh, __nv_bfloat16* __restrict__ hol,
    int b0, int j0, int lane, int wm, int wn, float (&acc)[4][2][4])
{
    #pragma unroll
    for (int rr = 0; rr < 2; ++rr) {
        const int b = b0 + wm * 16 + (lane >> 2) + rr * 8;
        #pragma unroll
        for (int nt = 0; nt < 2; ++nt) {
            const int jb = j0 + wn * 16 + nt * 8 + (lane & 3) * 2;
            float hv[2];
            #pragma unroll
            for (int jj = 0; jj < 2; ++jj) {
                const int j = jb + jj;
                const int o = rr * 2 + jj;
                const float r = siga(acc[0][nt][o] + bih[j] + bhh[j]);
                const float z = siga(acc[1][nt][o] + bih[Hn + j] + bhh[Hn + j]);
                const float n = tanha(acc[2][nt][o] + bih[2 * Hn + j]
                                      + r * (acc[3][nt][o] + bhh[2 * Hn + j]));
                const float hp = hpf[(size_t)b * Hn + j];
                hv[jj] = (1.f - z) * n + z * hp;
            }
            *(float2*)(hof + (size_t)b * Hn + jb) = make_float2(hv[0], hv[1]);
            const __nv_bfloat16 h0 = __float2bfloat16(hv[0]);
            const __nv_bfloat16 h1 = __float2bfloat16(hv[1]);
            const __nv_bfloat16 l0 = __float2bfloat16(hv[0] - __bfloat162float(h0));
            const __nv_bfloat16 l1 = __float2bfloat16(hv[1] - __bfloat162float(h1));
            *(u32*)(hoh + (size_t)b * Hn + jb) =
                (u32)__bfloat16_as_ushort(h0) | ((u32)__bfloat16_as_ushort(h1) << 16);
            *(u32*)(hol + (size_t)b * Hn + jb) =
                (u32)__bfloat16_as_ushort(l0) | ((u32)__bfloat16_as_ushort(l1) << 16);
        }
    }
}

// ---------------- persistent scan kernel ----------------
// grid 128 x 512 threads, 1 CTA/SM. Group = 4 CTAs sharing b0; groups independent.
// 16 warps: wm = wid>>2 (m16 tile), wn = wid&3 (n16 tile per gate).
__global__ void __launch_bounds__(NT, 1)
gru_scan(const float* __restrict__ bih0, const float* __restrict__ bhh0,
         const float* __restrict__ bih1, const float* __restrict__ bhh1,
         const float* __restrict__ fcw, const float* __restrict__ fcb,
         float* __restrict__ out)
{
    extern __shared__ char sm[];
    const u32 sb = s2u(sm);
    const int tid = threadIdx.x, lane = tid & 31, wid = tid >> 5;
    const int wm = wid >> 2, wn = wid & 3;
    const int cta = blockIdx.x;
    const int grp = cta >> 2, member = cta & 3;
    const int b0 = grp * 64, j0 = member * 64;

    int cc = 0;
    stage_any(0, 0, sb, tid, b0, j0);     // prime: x-chunk of superstep 0

    for (int l = 0; l <= Tn; ++l) {
        const int pv = (l + 1) & 1, cu = l & 1;
        const int kbeg = (l < Tn) ? 0 : 5;
        const int kend = (l >= 1) ? 13 : 5;

        float acc[4][2][4] = {};

        if (l == Tn) stage_any(5, l, sb + (cc & 1) * BUFB, tid, b0, j0);  // re-prime

        for (int k = kbeg; k < kend; ++k) {
            const int buf = cc & 1;
            __syncthreads();                         // prev compute done; other buf free
            bool havenext = false;
            if (k + 1 < kend) {
                stage_any(k + 1, l, sb + (buf ^ 1) * BUFB, tid, b0, j0);
                havenext = true;
            } else if (l + 1 <= Tn - 1) {            // prefetch next superstep's x-chunk
                stage_any(0, l + 1, sb + (buf ^ 1) * BUFB, tid, b0, j0);
                havenext = true;
            }
            if (havenext) asm volatile("cp.async.wait_group 1;");
            else          asm volatile("cp.async.wait_group 0;");
            __syncthreads();

            const u32 base = sb + buf * BUFB;
            if (k == 0)      compute_chunk<4, 2>(base, lane, wm, wn, acc);
            else if (k <= 4) compute_chunk<8, 3>(base, lane, wm, wn, acc);
            else if (k <= 8) compute_chunk<8, 2>(base, lane, wm, wn, acc);
            else             compute_chunk<8, 3>(base, lane, wm, wn, acc);

            if (k == 4) {   // layer0 complete -> h1[cu]
                epilogue(bih0, bhh0, g_h1f[pv], g_h1f[cu], g_h1h[cu], g_h1l[cu],
                         b0, j0, lane, wm, wn, acc);
                #pragma unroll
                for (int a = 0; a < 4; ++a)
                #pragma unroll
                for (int n2 = 0; n2 < 2; ++n2)
                #pragma unroll
                for (int q = 0; q < 4; ++q) acc[a][n2][q] = 0.f;
            }
            ++cc;
        }

        if (l >= 1) {   // layer1 (t=l-1) complete -> h2[pv]
            epilogue(bih1, bhh1, g_h2f[cu], g_h2f[pv], g_h2h[pv], g_h2l[pv],
                     b0, j0, lane, wm, wn, acc);
        }

        // ---- group barrier (release-acquire) ----
        __threadfence();
        __syncthreads();
        if (tid == 0) {
            atomicAdd(&g_bar[grp], 1u);
            const unsigned target = 4u * (unsigned)(l + 1);
            while (atomicAdd(&g_bar[grp], 0u) < target) { }
            __threadfence();
        }
        __syncthreads();
    }

    // ---- fc tail: 16 warps, one row each; member covers rows b0+member*16..+15 ----
    const float* fh = g_h2f[(Tn - 1) & 1];
    {
        const int b = b0 + member * 16 + wid;
        const float* h = fh + (size_t)b * Hn;
        float a0 = 0.f, a1 = 0.f, a2 = 0.f, a3 = 0.f;
        for (int kk = lane; kk < Hn; kk += 32) {
            const float hv = h[kk];
            a0 = fmaf(hv, fcw[kk], a0);
            a1 = fmaf(hv, fcw[Hn + kk], a1);
            a2 = fmaf(hv, fcw[2 * Hn + kk], a2);
            a3 = fmaf(hv, fcw[3 * Hn + kk], a3);
        }
        #pragma unroll
        for (int s = 16; s; s >>= 1) {
            a0 += __shfl_xor_sync(0xFFFFFFFFu, a0, s);
            a1 += __shfl_xor_sync(0xFFFFFFFFu, a1, s);
            a2 += __shfl_xor_sync(0xFFFFFFFFu, a2, s);
            a3 += __shfl_xor_sync(0xFFFFFFFFu, a3, s);
        }
        if (lane == 0) {
            out[b * 4 + 0] = 2.f * sigf(a0 + fcb[0]) - 1.f;
            out[b * 4 + 1] = 2.f * sigf(a1 + fcb[1]) - 1.f;
            out[b * 4 + 2] = 2.f * sigf(a2 + fcb[2]) - 1.f;
            out[b * 4 + 3] = 2.f * sigf(a3 + fcb[3]) - 1.f;
        }
    }
}

// ---------------- prologue: all splits in one kernel ----------------
__global__ void split_all(const float* __restrict__ Whh0, const float* __restrict__ Wih1,
                          const float* __restrict__ Whh1, const float* __restrict__ Wih0,
                          const float* __restrict__ x)
{
    const size_t NW = (size_t)G3H * Hn;
    const size_t NI = (size_t)G3H * XP;
    const size_t NX = (size_t)Tn * Bn * XP;
    const size_t i = (size_t)blockIdx.x * blockDim.x + threadIdx.x;
    float v; __nv_bfloat16 *hi, *lo; size_t o;
    if (i < NW)            { o = i;            v = Whh0[o]; hi = g_whh0h; lo = g_whh0l; }
    else if (i < 2 * NW)   { o = i - NW;       v = Wih1[o]; hi = g_wih1h; lo = g_wih1l; }
    else if (i < 3 * NW)   { o = i - 2 * NW;   v = Whh1[o]; hi = g_whh1h; lo = g_whh1l; }
    else if (i < 3 * NW + NI) {
        o = i - 3 * NW;
        const size_t r = o >> 5; const int k = (int)(o & 31);
        v = (k < In0) ? Wih0[r * In0 + k] : 0.f; hi = g_wi0h; lo = g_wi0l;
    } else if (i < 3 * NW + NI + NX) {
        o = i - 3 * NW - NI;
        const size_t r = o >> 5; const int k = (int)(o & 31);
        v = (k < In0) ? x[r * In0 + k] : 0.f; hi = g_xsh; lo = g_xsl;
    } else return;
    const __nv_bfloat16 h = __float2bfloat16(v);
    hi[o] = h;
    lo[o] = __float2bfloat16(v - __bfloat162float(h));
}

extern "C" void kernel_launch(void* const* d_in, const int* in_sizes, int n_in,
                              void* d_out, int out_size)
{
    const float* x    = (const float*)d_in[0];
    const float* Wih0 = (const float*)d_in[1];
    const float* Whh0 = (const float*)d_in[2];
    const float* bih0 = (const float*)d_in[3];
    const float* bhh0 = (const float*)d_in[4];
    const float* Wih1 = (const float*)d_in[5];
    const float* Whh1 = (const float*)d_in[6];
    const float* bih1 = (const float*)d_in[7];
    const float* bhh1 = (const float*)d_in[8];
    const float* fcw  = (const float*)d_in[9];
    const float* fcb  = (const float*)d_in[10];
    float* out = (float*)d_out;
    (void)in_sizes; (void)n_in; (void)out_size;

    cudaFuncSetAttribute(gru_scan, cudaFuncAttributeMaxDynamicSharedMemorySize, SMEM_DYN);

    // prologue splits
    {
        const size_t total = 3 * (size_t)G3H * Hn + (size_t)G3H * XP + (size_t)Tn * Bn * XP;
        split_all<<<(unsigned)((total + 255) / 256), 256>>>(Whh0, Wih1, Whh1, Wih0, x);
    }
    // zero barrier counters + ring slot 1 ("previous" state at t=0)
    {
        void* p;
        const size_t nf = sizeof(float) * (size_t)Bn * Hn;
        const size_t nb = sizeof(__nv_bfloat16) * (size_t)Bn * Hn;
        cudaGetSymbolAddress(&p, g_bar); cudaMemsetAsync(p, 0, sizeof(unsigned) * 32, 0);
        cudaGetSymbolAddress(&p, g_h1f); cudaMemsetAsync((char*)p + nf, 0, nf, 0);
        cudaGetSymbolAddress(&p, g_h2f); cudaMemsetAsync((char*)p + nf, 0, nf, 0);
        cudaGetSymbolAddress(&p, g_h1h); cudaMemsetAsync((char*)p + nb, 0, nb, 0);
        cudaGetSymbolAddress(&p, g_h1l); cudaMemsetAsync((char*)p + nb, 0, nb, 0);
        cudaGetSymbolAddress(&p, g_h2h); cudaMemsetAsync((char*)p + nb, 0, nb, 0);
        cudaGetSymbolAddress(&p, g_h2l); cudaMemsetAsync((char*)p + nb, 0, nb, 0);
    }

    gru_scan<<<128, NT, SMEM_DYN>>>(bih0, bhh0, bih1, bhh1, fcw, fcb, out);
}

// round 14
// speedup vs baseline: 1.5099x; 1.5099x over previous
#include <cuda_runtime.h>
#include <cuda_bf16.h>
#include <math.h>

#define Tn 128
#define Bn 2048
#define Hn 256
#define In0 18
#define G3H 768
#define XP 32          // x K padded to 32 (one half-chunk)

typedef unsigned int u32;

// ---------------- device global scratch ----------------
__device__ float          g_h1f[2][Bn * Hn], g_h2f[2][Bn * Hn];
__device__ __nv_bfloat16  g_h1h[2][Bn * Hn], g_h1l[2][Bn * Hn];
__device__ __nv_bfloat16  g_h2h[2][Bn * Hn], g_h2l[2][Bn * Hn];
__device__ __nv_bfloat16  g_whh0h[G3H * Hn], g_whh0l[G3H * Hn];
__device__ __nv_bfloat16  g_wih1h[G3H * Hn], g_wih1l[G3H * Hn];
__device__ __nv_bfloat16  g_whh1h[G3H * Hn], g_whh1l[G3H * Hn];
__device__ __nv_bfloat16  g_wi0h[G3H * XP],  g_wi0l[G3H * XP];
__device__ __nv_bfloat16  g_xsh[(size_t)Tn * Bn * XP], g_xsl[(size_t)Tn * Bn * XP];
__device__ unsigned       g_bar[32];

__device__ __forceinline__ float sigf(float x) { return 1.f / (1.f + expf(-x)); }
__device__ __forceinline__ float tanha(float x) {
    float y; asm("tanh.approx.f32 %0, %1;" : "=f"(y) : "f"(x)); return y;
}
__device__ __forceinline__ float siga(float x) { return fmaf(tanha(0.5f * x), 0.5f, 0.5f); }

// ---------------- PTX helpers ----------------
__device__ __forceinline__ u32 s2u(const void* p) { return (u32)__cvta_generic_to_shared(p); }
__device__ __forceinline__ void ldsm4(u32 (&d)[4], u32 addr) {
    asm volatile("ldmatrix.sync.aligned.m8n8.x4.shared.b16 {%0,%1,%2,%3}, [%4];"
                 : "=r"(d[0]), "=r"(d[1]), "=r"(d[2]), "=r"(d[3]) : "r"(addr));
}
__device__ __forceinline__ void cpa(u32 dst, const void* src) {
    asm volatile("cp.async.cg.shared.global [%0], [%1], 16;" :: "r"(dst), "l"(src));
}
__device__ __forceinline__ void mma(float (&d)[4], const u32 (&a)[4], u32 b0, u32 b1) {
    asm("mma.sync.aligned.m16n8k16.row.col.f32.bf16.bf16.f32 "
        "{%0,%1,%2,%3},{%4,%5,%6,%7},{%8,%9},{%0,%1,%2,%3};"
        : "+f"(d[0]), "+f"(d[1]), "+f"(d[2]), "+f"(d[3])
        : "r"(a[0]), "r"(a[1]), "r"(a[2]), "r"(a[3]), "r"(b0), "r"(b1));
}

// smem: 2 dynamic buffers x 64KB. Buffer: A hi | A lo | W hi | W lo.
#define BUFB 65536
#define SMEM_DYN (2 * BUFB)

// ---------------- staging (QW quads per row: 8 => K64, 4 => K32) ----------------
template<int QW>
__device__ __forceinline__ void stage_chunk(
    u32 base, int tid, int j0,
    const __nv_bfloat16* __restrict__ Ah, const __nv_bfloat16* __restrict__ Al, int lda,
    const __nv_bfloat16* __restrict__ Wh, const __nv_bfloat16* __restrict__ Wl, int ldw)
{
    const u32 aH = base, aL = base + QW * 1024;
    const u32 wH = base + 16384, wL = wH + QW * 192 * 16;
    #pragma unroll
    for (int i = 0; i < (64 * QW) / 256; ++i) {
        const int idx = tid + i * 256;
        const int r = idx / QW, q = idx % QW;
        const u32 off = (u32)((r * QW + (q ^ (r & (QW - 1)))) * 16);
        cpa(aH + off, Ah + (size_t)r * lda + q * 8);
        cpa(aL + off, Al + (size_t)r * lda + q * 8);
    }
    #pragma unroll
    for (int i = 0; i < (192 * QW) / 256; ++i) {
        const int idx = tid + i * 256;
        const int cl = idx / QW, q = idx % QW;
        const int grow = (cl >> 6) * Hn + j0 + (cl & 63);
        const u32 off = (u32)((cl * QW + (q ^ (cl & (QW - 1)))) * 16);
        cpa(wH + off, Wh + (size_t)grow * ldw + q * 8);
        cpa(wL + off, Wl + (size_t)grow * ldw + q * 8);
    }
    asm volatile("cp.async.commit_group;");
}

// resolve chunk source & stage. k: 0=x-chunk(QW4), 1..4 whh0, 5..8 wih1, 9..12 whh1.
__device__ __forceinline__ void stage_any(int k, int l, u32 base, int tid, int b0, int j0)
{
    const int pv = (l + 1) & 1, cu = l & 1;
    if (k == 0) {
        stage_chunk<4>(base, tid, j0,
                       g_xsh + ((size_t)l * Bn + b0) * XP, g_xsl + ((size_t)l * Bn + b0) * XP, XP,
                       g_wi0h, g_wi0l, XP);
    } else if (k <= 4) {
        const int c = k - 1;
        stage_chunk<8>(base, tid, j0,
                       g_h1h[pv] + (size_t)b0 * Hn + c * 64, g_h1l[pv] + (size_t)b0 * Hn + c * 64, Hn,
                       g_whh0h + c * 64, g_whh0l + c * 64, Hn);
    } else if (k <= 8) {
        const int c = k - 5;
        stage_chunk<8>(base, tid, j0,
                       g_h1h[pv] + (size_t)b0 * Hn + c * 64, g_h1l[pv] + (size_t)b0 * Hn + c * 64, Hn,
                       g_wih1h + c * 64, g_wih1l + c * 64, Hn);
    } else {
        const int c = k - 9;
        stage_chunk<8>(base, tid, j0,
                       g_h2h[cu] + (size_t)b0 * Hn + c * 64, g_h2l[cu] + (size_t)b0 * Hn + c * 64, Hn,
                       g_whh1h + c * 64, g_whh1l + c * 64, Hn);
    }
}

// ---------------- compute: acc sets 0=R 1=Z 2=current-n-target ----------------
// warp tile m32 (wm) x n16 per gate (wn). gate g3 -> acc set g3.
template<int QW>
__device__ __forceinline__ void compute_chunk(
    u32 base, int lane, int wm, int wn, float (&acc)[3][2][2][4])
{
    const u32 aH = base, aL = base + QW * 1024;
    const u32 wH = base + 16384, wL = wH + QW * 192 * 16;
    const int arow_f = (lane & 7) + ((lane >> 3) & 1) * 8;
    const int akg    = (lane >> 4) & 1;
    const int brow_f = (lane & 7) + ((lane >> 4) & 1) * 8;
    const int bkg    = (lane >> 3) & 1;
    #pragma unroll
    for (int s = 0; s < QW / 2; ++s) {
        u32 ah[2][4], al[2][4];
        #pragma unroll
        for (int mt = 0; mt < 2; ++mt) {
            const int r = wm * 32 + mt * 16 + arow_f;
            const int g = s * 2 + akg;
            const u32 off = (u32)((r * QW + (g ^ (r & (QW - 1)))) * 16);
            ldsm4(ah[mt], aH + off);
            ldsm4(al[mt], aL + off);
        }
        #pragma unroll
        for (int g3 = 0; g3 < 3; ++g3) {
            const int cl = g3 * 64 + wn * 16 + brow_f;
            const int g = s * 2 + bkg;
            const u32 off = (u32)((cl * QW + (g ^ (cl & (QW - 1)))) * 16);
            u32 bh[4], bl[4];
            ldsm4(bh, wH + off);
            ldsm4(bl, wL + off);
            #pragma unroll
            for (int p = 0; p < 3; ++p) {             // hi*hi, lo*hi, hi*lo
                const u32 (*aa)[4] = (p == 1) ? al : ah;
                const u32* bb = (p == 2) ? bl : bh;
                #pragma unroll
                for (int mt = 0; mt < 2; ++mt) {
                    mma(acc[g3][mt][0], aa[mt], bb[0], bb[1]);
                    mma(acc[g3][mt][1], aa[mt], bb[2], bb[3]);
                }
            }
        }
    }
}

// ---------------- GRU gate epilogue (xn from smem stash, hn = acc set 2) ----------------
__device__ __forceinline__ void epilogue(
    const float* __restrict__ bih, const float* __restrict__ bhh,
    const float* __restrict__ hpf, float* __restrict__ hof,
    __nv_bfloat16* __restrict__ hoh, __nv_bfloat16* __restrict__ hol,
    int b0, int j0, int lane, int wm, int wn, int tid,
    float (&acc)[3][2][2][4], const float (*stash)[256])
{
    #pragma unroll
    for (int mt = 0; mt < 2; ++mt)
    #pragma unroll
    for (int rr = 0; rr < 2; ++rr) {
        const int b = b0 + wm * 32 + mt * 16 + (lane >> 2) + rr * 8;
        #pragma unroll
        for (int nt = 0; nt < 2; ++nt) {
            const int jb = j0 + wn * 16 + nt * 8 + (lane & 3) * 2;
            float hv[2];
            #pragma unroll
            for (int jj = 0; jj < 2; ++jj) {
                const int j = jb + jj;
                const int o = rr * 2 + jj;
                const float xn = stash[mt * 8 + nt * 4 + o][tid];
                const float r = siga(acc[0][mt][nt][o] + bih[j] + bhh[j]);
                const float z = siga(acc[1][mt][nt][o] + bih[Hn + j] + bhh[Hn + j]);
                const float n = tanha(xn + bih[2 * Hn + j]
                                      + r * (acc[2][mt][nt][o] + bhh[2 * Hn + j]));
                const float hp = hpf[(size_t)b * Hn + j];
                hv[jj] = (1.f - z) * n + z * hp;
            }
            *(float2*)(hof + (size_t)b * Hn + jb) = make_float2(hv[0], hv[1]);
            const __nv_bfloat16 h0 = __float2bfloat16(hv[0]);
            const __nv_bfloat16 h1 = __float2bfloat16(hv[1]);
            const __nv_bfloat16 l0 = __float2bfloat16(hv[0] - __bfloat162float(h0));
            const __nv_bfloat16 l1 = __float2bfloat16(hv[1] - __bfloat162float(h1));
            *(u32*)(hoh + (size_t)b * Hn + jb) =
                (u32)__bfloat16_as_ushort(h0) | ((u32)__bfloat16_as_ushort(h1) << 16);
            *(u32*)(hol + (size_t)b * Hn + jb) =
                (u32)__bfloat16_as_ushort(l0) | ((u32)__bfloat16_as_ushort(l1) << 16);
        }
    }
}

// ---------------- persistent scan kernel ----------------
// grid 128 x 256 threads, 1 CTA/SM. Group = 4 CTAs sharing b0; groups independent.
__global__ void __launch_bounds__(256, 1)
gru_scan(const float* __restrict__ bih0, const float* __restrict__ bhh0,
         const float* __restrict__ bih1, const float* __restrict__ bhh1,
         const float* __restrict__ fcw, const float* __restrict__ fcb,
         float* __restrict__ out)
{
    extern __shared__ char sm[];
    __shared__ float s_stash[16][256];               // XN stash: [frag-idx][tid]
    const u32 sb = s2u(sm);
    const int tid = threadIdx.x, lane = tid & 31, wid = tid >> 5;
    const int wm = wid >> 2, wn = wid & 3;
    const int cta = blockIdx.x;
    const int grp = cta >> 2, member = cta & 3;
    const int b0 = grp * 64, j0 = member * 64;

    int cc = 0;
    stage_any(0, 0, sb, tid, b0, j0);                // prime: x-chunk of superstep 0

    for (int l = 0; l <= Tn; ++l) {
        const int pv = (l + 1) & 1, cu = l & 1;
        const int kbeg = (l < Tn) ? 0 : 5;
        const int kend = (l >= 1) ? 13 : 5;

        float acc[3][2][2][4] = {};

        if (l == Tn) stage_any(5, l, sb + (cc & 1) * BUFB, tid, b0, j0);  // re-prime

        for (int k = kbeg; k < kend; ++k) {
            const int buf = cc & 1;
            __syncthreads();                         // prev compute done; other buf free
            bool havenext = false;
            if (k + 1 < kend) {
                stage_any(k + 1, l, sb + (buf ^ 1) * BUFB, tid, b0, j0);
                havenext = true;
            } else if (l + 1 <= Tn - 1) {            // prefetch next superstep's x-chunk
                stage_any(0, l + 1, sb + (buf ^ 1) * BUFB, tid, b0, j0);
                havenext = true;
            }
            if (havenext) asm volatile("cp.async.wait_group 1;");
            else          asm volatile("cp.async.wait_group 0;");
            __syncthreads();

            const u32 base = sb + buf * BUFB;
            if (k == 0) compute_chunk<4>(base, lane, wm, wn, acc);
            else        compute_chunk<8>(base, lane, wm, wn, acc);

            if (k == 0 || k == 8) {                  // XN complete -> stash, reuse set 2 for HN
                #pragma unroll
                for (int mt = 0; mt < 2; ++mt)
                #pragma unroll
                for (int nt = 0; nt < 2; ++nt)
                #pragma unroll
                for (int q = 0; q < 4; ++q) {
                    s_stash[mt * 8 + nt * 4 + q][tid] = acc[2][mt][nt][q];
                    acc[2][mt][nt][q] = 0.f;
                }
            }

            if (k == 4) {                            // layer0 complete -> h1[cu]
                epilogue(bih0, bhh0, g_h1f[pv], g_h1f[cu], g_h1h[cu], g_h1l[cu],
                         b0, j0, lane, wm, wn, tid, acc, s_stash);
                #pragma unroll
                for (int a = 0; a < 3; ++a)
                #pragma unroll
                for (int mt = 0; mt < 2; ++mt)
                #pragma unroll
                for (int nt = 0; nt < 2; ++nt)
                #pragma unroll
                for (int q = 0; q < 4; ++q) acc[a][mt][nt][q] = 0.f;
            }
            ++cc;
        }

        if (l >= 1) {                                // layer1 (t=l-1) complete -> h2[pv]
            epilogue(bih1, bhh1, g_h2f[cu], g_h2f[pv], g_h2h[pv], g_h2l[pv],
                     b0, j0, lane, wm, wn, tid, acc, s_stash);
        }

        // ---- group barrier (release-acquire) ----
        __threadfence();
        __syncthreads();
        if (tid == 0) {
            atomicAdd(&g_bar[grp], 1u);
            const unsigned target = 4u * (unsigned)(l + 1);
            while (atomicAdd(&g_bar[grp], 0u) < target) { }
            __threadfence();
        }
        __syncthreads();
    }

    // ---- fc tail: member handles rows b0+member*16 .. +15 ----
    const float* fh = g_h2f[(Tn - 1) & 1];
    for (int rr = wid; rr < 16; rr += 8) {
        const int b = b0 + member * 16 + rr;
        const float* h = fh + (size_t)b * Hn;
        float a0 = 0.f, a1 = 0.f, a2 = 0.f, a3 = 0.f;
        for (int kk = lane; kk < Hn; kk += 32) {
            const float hv = h[kk];
            a0 = fmaf(hv, fcw[kk], a0);
            a1 = fmaf(hv, fcw[Hn + kk], a1);
            a2 = fmaf(hv, fcw[2 * Hn + kk], a2);
            a3 = fmaf(hv, fcw[3 * Hn + kk], a3);
        }
        #pragma unroll
        for (int s = 16; s; s >>= 1) {
            a0 += __shfl_xor_sync(0xFFFFFFFFu, a0, s);
            a1 += __shfl_xor_sync(0xFFFFFFFFu, a1, s);
            a2 += __shfl_xor_sync(0xFFFFFFFFu, a2, s);
            a3 += __shfl_xor_sync(0xFFFFFFFFu, a3, s);
        }
        if (lane == 0) {
            out[b * 4 + 0] = 2.f * sigf(a0 + fcb[0]) - 1.f;
            out[b * 4 + 1] = 2.f * sigf(a1 + fcb[1]) - 1.f;
            out[b * 4 + 2] = 2.f * sigf(a2 + fcb[2]) - 1.f;
            out[b * 4 + 3] = 2.f * sigf(a3 + fcb[3]) - 1.f;
        }
    }
}

// ---------------- prologue: all splits in one kernel ----------------
__global__ void split_all(const float* __restrict__ Whh0, const float* __restrict__ Wih1,
                          const float* __restrict__ Whh1, const float* __restrict__ Wih0,
                          const float* __restrict__ x)
{
    const size_t NW = (size_t)G3H * Hn;
    const size_t NI = (size_t)G3H * XP;
    const size_t NX = (size_t)Tn * Bn * XP;
    const size_t i = (size_t)blockIdx.x * blockDim.x + threadIdx.x;
    float v; __nv_bfloat16 *hi, *lo; size_t o;
    if (i < NW)            { o = i;            v = Whh0[o]; hi = g_whh0h; lo = g_whh0l; }
    else if (i < 2 * NW)   { o = i - NW;       v = Wih1[o]; hi = g_wih1h; lo = g_wih1l; }
    else if (i < 3 * NW)   { o = i - 2 * NW;   v = Whh1[o]; hi = g_whh1h; lo = g_whh1l; }
    else if (i < 3 * NW + NI) {
        o = i - 3 * NW;
        const size_t r = o >> 5; const int k = (int)(o & 31);
        v = (k < In0) ? Wih0[r * In0 + k] : 0.f; hi = g_wi0h; lo = g_wi0l;
    } else if (i < 3 * NW + NI + NX) {
        o = i - 3 * NW - NI;
        const size_t r = o >> 5; const int k = (int)(o & 31);
        v = (k < In0) ? x[r * In0 + k] : 0.f; hi = g_xsh; lo = g_xsl;
    } else return;
    const __nv_bfloat16 h = __float2bfloat16(v);
    hi[o] = h;
    lo[o] = __float2bfloat16(v - __bfloat162float(h));
}

extern "C" void kernel_launch(void* const* d_in, const int* in_sizes, int n_in,
                              void* d_out, int out_size)
{
    const float* x    = (const float*)d_in[0];
    const float* Wih0 = (const float*)d_in[1];
    const float* Whh0 = (const float*)d_in[2];
    const float* bih0 = (const float*)d_in[3];
    const float* bhh0 = (const float*)d_in[4];
    const float* Wih1 = (const float*)d_in[5];
    const float* Whh1 = (const float*)d_in[6];
    const float* bih1 = (const float*)d_in[7];
    const float* bhh1 = (const float*)d_in[8];
    const float* fcw  = (const float*)d_in[9];
    const float* fcb  = (const float*)d_in[10];
    float* out = (float*)d_out;
    (void)in_sizes; (void)n_in; (void)out_size;

    cudaFuncSetAttribute(gru_scan, cudaFuncAttributeMaxDynamicSharedMemorySize, SMEM_DYN);

    // prologue splits
    {
        const size_t total = 3 * (size_t)G3H * Hn + (size_t)G3H * XP + (size_t)Tn * Bn * XP;
        split_all<<<(unsigned)((total + 255) / 256), 256>>>(Whh0, Wih1, Whh1, Wih0, x);
    }
    // zero barrier counters + ring slot 1 ("previous" state at t=0)
    {
        void* p;
        const size_t nf = sizeof(float) * (size_t)Bn * Hn;
        const size_t nb = sizeof(__nv_bfloat16) * (size_t)Bn * Hn;
        cudaGetSymbolAddress(&p, g_bar); cudaMemsetAsync(p, 0, sizeof(unsigned) * 32, 0);
        cudaGetSymbolAddress(&p, g_h1f); cudaMemsetAsync((char*)p + nf, 0, nf, 0);
        cudaGetSymbolAddress(&p, g_h2f); cudaMemsetAsync((char*)p + nf, 0, nf, 0);
        cudaGetSymbolAddress(&p, g_h1h); cudaMemsetAsync((char*)p + nb, 0, nb, 0);
        cudaGetSymbolAddress(&p, g_h1l); cudaMemsetAsync((char*)p + nb, 0, nb, 0);
        cudaGetSymbolAddress(&p, g_h2h); cudaMemsetAsync((char*)p + nb, 0, nb, 0);
        cudaGetSymbolAddress(&p, g_h2l); cudaMemsetAsync((char*)p + nb, 0, nb, 0);
    }

    gru_scan<<<128, 256, SMEM_DYN>>>(bih0, bhh0, bih1, bhh1, fcw, fcb, out);
}

// round 15
// speedup vs baseline: 1.5514x; 1.0275x over previous
#include <cuda_runtime.h>
#include <cuda_bf16.h>
#include <math.h>

#define Tn 128
#define Bn 2048
#define Hn 256
#define In0 18
#define G3H 768
#define XP 32          // x K padded to 32 (one half-chunk)

typedef unsigned int u32;

// ---------------- device global scratch ----------------
__device__ float          g_h1f[2][Bn * Hn], g_h2f[2][Bn * Hn];
__device__ __nv_bfloat16  g_h1h[2][Bn * Hn], g_h1l[2][Bn * Hn];
__device__ __nv_bfloat16  g_h2h[2][Bn * Hn], g_h2l[2][Bn * Hn];
__device__ __nv_bfloat16  g_whh0h[G3H * Hn], g_whh0l[G3H * Hn];
__device__ __nv_bfloat16  g_wih1h[G3H * Hn], g_wih1l[G3H * Hn];
__device__ __nv_bfloat16  g_whh1h[G3H * Hn], g_whh1l[G3H * Hn];
__device__ __nv_bfloat16  g_wi0h[G3H * XP],  g_wi0l[G3H * XP];
__device__ __nv_bfloat16  g_xsh[(size_t)Tn * Bn * XP], g_xsl[(size_t)Tn * Bn * XP];
__device__ unsigned       g_bar[32];

__device__ __forceinline__ float sigf(float x) { return 1.f / (1.f + expf(-x)); }
__device__ __forceinline__ float tanha(float x) {
    float y; asm("tanh.approx.f32 %0, %1;" : "=f"(y) : "f"(x)); return y;
}
__device__ __forceinline__ float siga(float x) { return fmaf(tanha(0.5f * x), 0.5f, 0.5f); }

// ---------------- PTX helpers ----------------
__device__ __forceinline__ u32 s2u(const void* p) { return (u32)__cvta_generic_to_shared(p); }
__device__ __forceinline__ void ldsm4(u32 (&d)[4], u32 addr) {
    asm volatile("ldmatrix.sync.aligned.m8n8.x4.shared.b16 {%0,%1,%2,%3}, [%4];"
                 : "=r"(d[0]), "=r"(d[1]), "=r"(d[2]), "=r"(d[3]) : "r"(addr));
}
__device__ __forceinline__ void cpa(u32 dst, const void* src) {
    asm volatile("cp.async.cg.shared.global [%0], [%1], 16;" :: "r"(dst), "l"(src));
}
__device__ __forceinline__ void mma(float (&d)[4], const u32 (&a)[4], u32 b0, u32 b1) {
    asm("mma.sync.aligned.m16n8k16.row.col.f32.bf16.bf16.f32 "
        "{%0,%1,%2,%3},{%4,%5,%6,%7},{%8,%9},{%0,%1,%2,%3};"
        : "+f"(d[0]), "+f"(d[1]), "+f"(d[2]), "+f"(d[3])
        : "r"(a[0]), "r"(a[1]), "r"(a[2]), "r"(a[3]), "r"(b0), "r"(b1));
}

// smem: 3 dynamic buffers x 64KB (3-stage pipeline). Buffer: A hi | A lo | W hi | W lo.
#define BUFB 65536
#define NBUF 3
#define SMEM_DYN (NBUF * BUFB)

// ---------------- staging (QW quads per row: 8 => K64, 4 => K32) ----------------
template<int QW>
__device__ __forceinline__ void stage_chunk(
    u32 base, int tid, int j0,
    const __nv_bfloat16* __restrict__ Ah, const __nv_bfloat16* __restrict__ Al, int lda,
    const __nv_bfloat16* __restrict__ Wh, const __nv_bfloat16* __restrict__ Wl, int ldw)
{
    const u32 aH = base, aL = base + QW * 1024;
    const u32 wH = base + 16384, wL = wH + QW * 192 * 16;
    #pragma unroll
    for (int i = 0; i < (64 * QW) / 256; ++i) {
        const int idx = tid + i * 256;
        const int r = idx / QW, q = idx % QW;
        const u32 off = (u32)((r * QW + (q ^ (r & (QW - 1)))) * 16);
        cpa(aH + off, Ah + (size_t)r * lda + q * 8);
        cpa(aL + off, Al + (size_t)r * lda + q * 8);
    }
    #pragma unroll
    for (int i = 0; i < (192 * QW) / 256; ++i) {
        const int idx = tid + i * 256;
        const int cl = idx / QW, q = idx % QW;
        const int grow = (cl >> 6) * Hn + j0 + (cl & 63);
        const u32 off = (u32)((cl * QW + (q ^ (cl & (QW - 1)))) * 16);
        cpa(wH + off, Wh + (size_t)grow * ldw + q * 8);
        cpa(wL + off, Wl + (size_t)grow * ldw + q * 8);
    }
    asm volatile("cp.async.commit_group;");
}

// resolve chunk source & stage. k: 0=x-chunk(QW4), 1..4 whh0, 5..8 wih1, 9..12 whh1.
__device__ __forceinline__ void stage_any(int k, int l, u32 base, int tid, int b0, int j0)
{
    const int pv = (l + 1) & 1, cu = l & 1;
    if (k == 0) {
        stage_chunk<4>(base, tid, j0,
                       g_xsh + ((size_t)l * Bn + b0) * XP, g_xsl + ((size_t)l * Bn + b0) * XP, XP,
                       g_wi0h, g_wi0l, XP);
    } else if (k <= 4) {
        const int c = k - 1;
        stage_chunk<8>(base, tid, j0,
                       g_h1h[pv] + (size_t)b0 * Hn + c * 64, g_h1l[pv] + (size_t)b0 * Hn + c * 64, Hn,
                       g_whh0h + c * 64, g_whh0l + c * 64, Hn);
    } else if (k <= 8) {
        const int c = k - 5;
        stage_chunk<8>(base, tid, j0,
                       g_h1h[pv] + (size_t)b0 * Hn + c * 64, g_h1l[pv] + (size_t)b0 * Hn + c * 64, Hn,
                       g_wih1h + c * 64, g_wih1l + c * 64, Hn);
    } else {
        const int c = k - 9;
        stage_chunk<8>(base, tid, j0,
                       g_h2h[cu] + (size_t)b0 * Hn + c * 64, g_h2l[cu] + (size_t)b0 * Hn + c * 64, Hn,
                       g_whh1h + c * 64, g_whh1l + c * 64, Hn);
    }
}

// ---------------- compute: acc sets 0=R 1=Z 2=current-n-target ----------------
template<int QW>
__device__ __forceinline__ void compute_chunk(
    u32 base, int lane, int wm, int wn, float (&acc)[3][2][2][4])
{
    const u32 aH = base, aL = base + QW * 1024;
    const u32 wH = base + 16384, wL = wH + QW * 192 * 16;
    const int arow_f = (lane & 7) + ((lane >> 3) & 1) * 8;
    const int akg    = (lane >> 4) & 1;
    const int brow_f = (lane & 7) + ((lane >> 4) & 1) * 8;
    const int bkg    = (lane >> 3) & 1;
    #pragma unroll
    for (int s = 0; s < QW / 2; ++s) {
        u32 ah[2][4], al[2][4];
        #pragma unroll
        for (int mt = 0; mt < 2; ++mt) {
            const int r = wm * 32 + mt * 16 + arow_f;
            const int g = s * 2 + akg;
            const u32 off = (u32)((r * QW + (g ^ (r & (QW - 1)))) * 16);
            ldsm4(ah[mt], aH + off);
            ldsm4(al[mt], aL + off);
        }
        #pragma unroll
        for (int g3 = 0; g3 < 3; ++g3) {
            const int cl = g3 * 64 + wn * 16 + brow_f;
            const int g = s * 2 + bkg;
            const u32 off = (u32)((cl * QW + (g ^ (cl & (QW - 1)))) * 16);
            u32 bh[4], bl[4];
            ldsm4(bh, wH + off);
            ldsm4(bl, wL + off);
            #pragma unroll
            for (int p = 0; p < 3; ++p) {             // hi*hi, lo*hi, hi*lo
                const u32 (*aa)[4] = (p == 1) ? al : ah;
                const u32* bb = (p == 2) ? bl : bh;
                #pragma unroll
                for (int mt = 0; mt < 2; ++mt) {
                    mma(acc[g3][mt][0], aa[mt], bb[0], bb[1]);
                    mma(acc[g3][mt][1], aa[mt], bb[2], bb[3]);
                }
            }
        }
    }
}

// ---------------- GRU gate epilogue (xn from smem stash, hn = acc set 2) ----------------
__device__ __forceinline__ void epilogue(
    const float* __restrict__ bih, const float* __restrict__ bhh,
    const float* __restrict__ hpf, float* __restrict__ hof,
    __nv_bfloat16* __restrict__ hoh, __nv_bfloat16* __restrict__ hol,
    int b0, int j0, int lane, int wm, int wn, int tid,
    float (&acc)[3][2][2][4], const float (*stash)[256])
{
    #pragma unroll
    for (int mt = 0; mt < 2; ++mt)
    #pragma unroll
    for (int rr = 0; rr < 2; ++rr) {
        const int b = b0 + wm * 32 + mt * 16 + (lane >> 2) + rr * 8;
        #pragma unroll
        for (int nt = 0; nt < 2; ++nt) {
            const int jb = j0 + wn * 16 + nt * 8 + (lane & 3) * 2;
            float hv[2];
            #pragma unroll
            for (int jj = 0; jj < 2; ++jj) {
                const int j = jb + jj;
                const int o = rr * 2 + jj;
                const float xn = stash[mt * 8 + nt * 4 + o][tid];
                const float r = siga(acc[0][mt][nt][o] + bih[j] + bhh[j]);
                const float z = siga(acc[1][mt][nt][o] + bih[Hn + j] + bhh[Hn + j]);
                const float n = tanha(xn + bih[2 * Hn + j]
                                      + r * (acc[2][mt][nt][o] + bhh[2 * Hn + j]));
                const float hp = hpf[(size_t)b * Hn + j];
                hv[jj] = (1.f - z) * n + z * hp;
            }
            *(float2*)(hof + (size_t)b * Hn + jb) = make_float2(hv[0], hv[1]);
            const __nv_bfloat16 h0 = __float2bfloat16(hv[0]);
            const __nv_bfloat16 h1 = __float2bfloat16(hv[1]);
            const __nv_bfloat16 l0 = __float2bfloat16(hv[0] - __bfloat162float(h0));
            const __nv_bfloat16 l1 = __float2bfloat16(hv[1] - __bfloat162float(h1));
            *(u32*)(hoh + (size_t)b * Hn + jb) =
                (u32)__bfloat16_as_ushort(h0) | ((u32)__bfloat16_as_ushort(h1) << 16);
            *(u32*)(hol + (size_t)b * Hn + jb) =
                (u32)__bfloat16_as_ushort(l0) | ((u32)__bfloat16_as_ushort(l1) << 16);
        }
    }
}

// ---------------- persistent scan kernel ----------------
// grid 128 x 256 threads, 1 CTA/SM. Group = 4 CTAs sharing b0; groups independent.
// 3-stage cp.async pipeline, ONE __syncthreads per chunk (CUTLASS multistage order).
__global__ void __launch_bounds__(256, 1)
gru_scan(const float* __restrict__ bih0, const float* __restrict__ bhh0,
         const float* __restrict__ bih1, const float* __restrict__ bhh1,
         const float* __restrict__ fcw, const float* __restrict__ fcb,
         float* __restrict__ out)
{
    extern __shared__ char sm[];
    __shared__ float s_stash[16][256];               // XN stash: [frag-idx][tid]
    const u32 sb = s2u(sm);
    const int tid = threadIdx.x, lane = tid & 31, wid = tid >> 5;
    const int wm = wid >> 2, wn = wid & 3;
    const int cta = blockIdx.x;
    const int grp = cta >> 2, member = cta & 3;
    const int b0 = grp * 64, j0 = member * 64;

    int ss = 0, cs = 0;                              // stage / compute ring counters
    // prime: item 0 of superstep 0 (x-chunk)
    stage_any(0, 0, sb, tid, b0, j0); ++ss;

    for (int l = 0; l <= Tn; ++l) {
        const int pv = (l + 1) & 1, cu = l & 1;
        const int kbeg = (l < Tn) ? 0 : 5;
        const int kend = (l >= 1) ? 13 : 5;
        const int n = kend - kbeg;
        const bool hx = (l + 1 <= Tn - 1);           // next superstep has an x-chunk
        const int m = n + (hx ? 1 : 0);              // items this superstep stages/owns

        if (l == Tn) {                               // nothing pre-staged (no xnext last time)
            stage_any(kbeg, l, sb + (ss % NBUF) * BUFB, tid, b0, j0); ++ss;
        }
        // stage item 1 (first post-barrier-dependent chunk)
        stage_any(kbeg + 1, l, sb + (ss % NBUF) * BUFB, tid, b0, j0); ++ss;

        float acc[3][2][2][4] = {};

        for (int j = 0; j < n; ++j) {
            const int k = kbeg + j;
            // wait for item j's data (2 items younger may be in flight)
            if (j < m - 1) asm volatile("cp.async.wait_group 1;");
            else           asm volatile("cp.async.wait_group 0;");
            __syncthreads();                         // data visible AND j-1 compute done everywhere
            // stage item j+2 (overwrites slot of item j-1 — safe after the sync)
            if (j + 2 < n) {
                stage_any(k + 2, l, sb + (ss % NBUF) * BUFB, tid, b0, j0); ++ss;
            } else if (j + 2 == n && hx) {
                stage_any(0, l + 1, sb + (ss % NBUF) * BUFB, tid, b0, j0); ++ss;
            }

            const u32 base = sb + (cs % NBUF) * BUFB; ++cs;
            if (k == 0) compute_chunk<4>(base, lane, wm, wn, acc);
            else        compute_chunk<8>(base, lane, wm, wn, acc);

            if (k == 0 || k == 8) {                  // XN complete -> stash, reuse set 2 for HN
                #pragma unroll
                for (int mt = 0; mt < 2; ++mt)
                #pragma unroll
                for (int nt = 0; nt < 2; ++nt)
                #pragma unroll
                for (int q = 0; q < 4; ++q) {
                    s_stash[mt * 8 + nt * 4 + q][tid] = acc[2][mt][nt][q];
                    acc[2][mt][nt][q] = 0.f;
                }
            }

            if (k == 4) {                            // layer0 complete -> h1[cu]
                epilogue(bih0, bhh0, g_h1f[pv], g_h1f[cu], g_h1h[cu], g_h1l[cu],
                         b0, j0, lane, wm, wn, tid, acc, s_stash);
                #pragma unroll
                for (int a = 0; a < 3; ++a)
                #pragma unroll
                for (int mt = 0; mt < 2; ++mt)
                #pragma unroll
                for (int nt = 0; nt < 2; ++nt)
                #pragma unroll
                for (int q = 0; q < 4; ++q) acc[a][mt][nt][q] = 0.f;
            }
        }

        if (l >= 1) {                                // layer1 (t=l-1) complete -> h2[pv]
            epilogue(bih1, bhh1, g_h2f[cu], g_h2f[pv], g_h2h[pv], g_h2l[pv],
                     b0, j0, lane, wm, wn, tid, acc, s_stash);
        }

        // ---- group barrier: release add, acquire poll with backoff ----
        __syncthreads();
        if (tid == 0) {
            __threadfence();
            atomicAdd(&g_bar[grp], 1u);
            const unsigned target = 4u * (unsigned)(l + 1);
            unsigned v;
            for (;;) {
                asm volatile("ld.acquire.gpu.global.u32 %0, [%1];"
                             : "=r"(v) : "l"(&g_bar[grp]) : "memory");
                if (v >= target) break;
                __nanosleep(64);
            }
        }
        __syncthreads();
    }

    // ---- fc tail: member handles rows b0+member*16 .. +15 ----
    const float* fh = g_h2f[(Tn - 1) & 1];
    for (int rr = wid; rr < 16; rr += 8) {
        const int b = b0 + member * 16 + rr;
        const float* h = fh + (size_t)b * Hn;
        float a0 = 0.f, a1 = 0.f, a2 = 0.f, a3 = 0.f;
        for (int kk = lane; kk < Hn; kk += 32) {
            const float hv = h[kk];
            a0 = fmaf(hv, fcw[kk], a0);
            a1 = fmaf(hv, fcw[Hn + kk], a1);
            a2 = fmaf(hv, fcw[2 * Hn + kk], a2);
            a3 = fmaf(hv, fcw[3 * Hn + kk], a3);
        }
        #pragma unroll
        for (int s = 16; s; s >>= 1) {
            a0 += __shfl_xor_sync(0xFFFFFFFFu, a0, s);
            a1 += __shfl_xor_sync(0xFFFFFFFFu, a1, s);
            a2 += __shfl_xor_sync(0xFFFFFFFFu, a2, s);
            a3 += __shfl_xor_sync(0xFFFFFFFFu, a3, s);
        }
        if (lane == 0) {
            out[b * 4 + 0] = 2.f * sigf(a0 + fcb[0]) - 1.f;
            out[b * 4 + 1] = 2.f * sigf(a1 + fcb[1]) - 1.f;
            out[b * 4 + 2] = 2.f * sigf(a2 + fcb[2]) - 1.f;
            out[b * 4 + 3] = 2.f * sigf(a3 + fcb[3]) - 1.f;
        }
    }
}

// ---------------- prologue: all splits in one kernel ----------------
__global__ void split_all(const float* __restrict__ Whh0, const float* __restrict__ Wih1,
                          const float* __restrict__ Whh1, const float* __restrict__ Wih0,
                          const float* __restrict__ x)
{
    const size_t NW = (size_t)G3H * Hn;
    const size_t NI = (size_t)G3H * XP;
    const size_t NX = (size_t)Tn * Bn * XP;
    const size_t i = (size_t)blockIdx.x * blockDim.x + threadIdx.x;
    float v; __nv_bfloat16 *hi, *lo; size_t o;
    if (i < NW)            { o = i;            v = Whh0[o]; hi = g_whh0h; lo = g_whh0l; }
    else if (i < 2 * NW)   { o = i - NW;       v = Wih1[o]; hi = g_wih1h; lo = g_wih1l; }
    else if (i < 3 * NW)   { o = i - 2 * NW;   v = Whh1[o]; hi = g_whh1h; lo = g_whh1l; }
    else if (i < 3 * NW + NI) {
        o = i - 3 * NW;
        const size_t r = o >> 5; const int k = (int)(o & 31);
        v = (k < In0) ? Wih0[r * In0 + k] : 0.f; hi = g_wi0h; lo = g_wi0l;
    } else if (i < 3 * NW + NI + NX) {
        o = i - 3 * NW - NI;
        const size_t r = o >> 5; const int k = (int)(o & 31);
        v = (k < In0) ? x[r * In0 + k] : 0.f; hi = g_xsh; lo = g_xsl;
    } else return;
    const __nv_bfloat16 h = __float2bfloat16(v);
    hi[o] = h;
    lo[o] = __float2bfloat16(v - __bfloat162float(h));
}

extern "C" void kernel_launch(void* const* d_in, const int* in_sizes, int n_in,
                              void* d_out, int out_size)
{
    const float* x    = (const float*)d_in[0];
    const float* Wih0 = (const float*)d_in[1];
    const float* Whh0 = (const float*)d_in[2];
    const float* bih0 = (const float*)d_in[3];
    const float* bhh0 = (const float*)d_in[4];
    const float* Wih1 = (const float*)d_in[5];
    const float* Whh1 = (const float*)d_in[6];
    const float* bih1 = (const float*)d_in[7];
    const float* bhh1 = (const float*)d_in[8];
    const float* fcw  = (const float*)d_in[9];
    const float* fcb  = (const float*)d_in[10];
    float* out = (float*)d_out;
    (void)in_sizes; (void)n_in; (void)out_size;

    cudaFuncSetAttribute(gru_scan, cudaFuncAttributeMaxDynamicSharedMemorySize, SMEM_DYN);

    // prologue splits
    {
        const size_t total = 3 * (size_t)G3H * Hn + (size_t)G3H * XP + (size_t)Tn * Bn * XP;
        split_all<<<(unsigned)((total + 255) / 256), 256>>>(Whh0, Wih1, Whh1, Wih0, x);
    }
    // zero barrier counters + ring slot 1 ("previous" state at t=0)
    {
        void* p;
        const size_t nf = sizeof(float) * (size_t)Bn * Hn;
        const size_t nb = sizeof(__nv_bfloat16) * (size_t)Bn * Hn;
        cudaGetSymbolAddress(&p, g_bar); cudaMemsetAsync(p, 0, sizeof(unsigned) * 32, 0);
        cudaGetSymbolAddress(&p, g_h1f); cudaMemsetAsync((char*)p + nf, 0, nf, 0);
        cudaGetSymbolAddress(&p, g_h2f); cudaMemsetAsync((char*)p + nf, 0, nf, 0);
        cudaGetSymbolAddress(&p, g_h1h); cudaMemsetAsync((char*)p + nb, 0, nb, 0);
        cudaGetSymbolAddress(&p, g_h1l); cudaMemsetAsync((char*)p + nb, 0, nb, 0);
        cudaGetSymbolAddress(&p, g_h2h); cudaMemsetAsync((char*)p + nb, 0, nb, 0);
        cudaGetSymbolAddress(&p, g_h2l); cudaMemsetAsync((char*)p + nb, 0, nb, 0);
    }

    gru_scan<<<128, 256, SMEM_DYN>>>(bih0, bhh0, bih1, bhh1, fcw, fcb, out);
}